// round 1
// baseline (speedup 1.0000x reference)
#include <cuda_runtime.h>
#include <cstdint>

#define NBLK 128
#define NTHR 128
#define NTOT (NBLK * NTHR)   // 16384 threads, 4 particles each = 65536
#define LHID 64

// Packed fp32x2 FMA (Blackwell FFMA2). Scalar halves in/out; ptxas coalesces
// the mov.b64 pack/unpack into aligned register pairs.
__device__ __forceinline__ void fma2p(float &dlo, float &dhi,
                                      float alo, float ahi,
                                      float blo, float bhi,
                                      float clo, float chi)
{
    asm("{\n\t"
        ".reg .b64 pa, pb, pc;\n\t"
        "mov.b64 pa, {%2, %3};\n\t"
        "mov.b64 pb, {%4, %5};\n\t"
        "mov.b64 pc, {%6, %7};\n\t"
        "fma.rn.f32x2 pc, pa, pb, pc;\n\t"
        "mov.b64 {%0, %1}, pc;\n\t"
        "}"
        : "=f"(dlo), "=f"(dhi)
        : "f"(alo), "f"(ahi), "f"(blo), "f"(bhi), "f"(clo), "f"(chi));
}

__global__ __launch_bounds__(NTHR, 1)
void mc_kernel(const float* __restrict__ x,
               const float* __restrict__ W1,
               const float* __restrict__ b1,
               const float* __restrict__ W2,
               const float* __restrict__ b2,
               const int*   __restrict__ n_steps,
               float*       __restrict__ out)
{
    // Weights duplicated pairwise so LDS.128 lands {w,w} in an aligned reg pair.
    __shared__ float sw[LHID * 8];   // per j: {A,A,B,B,b,b,C,C}

    const int tid = threadIdx.x;
    if (tid < LHID) {
        const float A  = W1[tid];          // W1[0][j]
        const float Bw = W1[LHID + tid];   // W1[1][j]
        const float bb = b1[tid];
        const float C  = W2[tid];          // W2[j][0]
        float* w = &sw[tid * 8];
        w[0] = A;  w[1] = A;
        w[2] = Bw; w[3] = Bw;
        w[4] = bb; w[5] = bb;
        w[6] = C;  w[7] = C;
    }
    const float b2s = b2[0];
    const int   T   = n_steps[0];
    __syncthreads();

    const int g = blockIdx.x * NTHR + tid;

    float p[4], v[4], u[4], a[4], skeep[4];
    bool everact[4];
    #pragma unroll
    for (int k = 0; k < 4; k++) {
        float4 st = ((const float4*)x)[g + k * NTOT];
        p[k] = st.x; v[k] = st.y; u[k] = st.z; a[k] = st.w;
        skeep[k]   = 0.0f;
        everact[k] = false;
    }

    // atanh(0.5): tanh(s+b2) <= 0.5  <=>  s+b2 <= ATH (monotone)
    const float ATH = 0.5493061443340549f;

    for (int t = 0; t < T; t++) {
        float pr[4], vr[4];
        #pragma unroll
        for (int k = 0; k < 4; k++) {
            const bool rst = p[k] <= -1.2f;
            pr[k] = rst ? -1.2f : p[k];
            vr[k] = rst ? 0.0f  : v[k];
        }

        // 2 accumulators (even/odd j) per particle pair -> 4 indep FMA chains
        float e0lo = 0.f, e0hi = 0.f, o0lo = 0.f, o0hi = 0.f;
        float e1lo = 0.f, e1hi = 0.f, o1lo = 0.f, o1hi = 0.f;

        #pragma unroll
        for (int j = 0; j < LHID; j++) {
            const float4 q0 = *(const float4*)&sw[j * 8];      // {A,A,B,B}
            const float4 q1 = *(const float4*)&sw[j * 8 + 4];  // {b,b,C,C}

            // pair 0: particles 0,1
            float t0lo, t0hi;
            fma2p(t0lo, t0hi, pr[0], pr[1], q0.x, q0.y, q1.x, q1.y); // p*A+b
            fma2p(t0lo, t0hi, vr[0], vr[1], q0.z, q0.w, t0lo, t0hi); // +v*B
            t0lo = fmaxf(t0lo, 0.0f);
            t0hi = fmaxf(t0hi, 0.0f);
            if (j & 1) fma2p(o0lo, o0hi, t0lo, t0hi, q1.z, q1.w, o0lo, o0hi);
            else       fma2p(e0lo, e0hi, t0lo, t0hi, q1.z, q1.w, e0lo, e0hi);

            // pair 1: particles 2,3
            float t1lo, t1hi;
            fma2p(t1lo, t1hi, pr[2], pr[3], q0.x, q0.y, q1.x, q1.y);
            fma2p(t1lo, t1hi, vr[2], vr[3], q0.z, q0.w, t1lo, t1hi);
            t1lo = fmaxf(t1lo, 0.0f);
            t1hi = fmaxf(t1hi, 0.0f);
            if (j & 1) fma2p(o1lo, o1hi, t1lo, t1hi, q1.z, q1.w, o1lo, o1hi);
            else       fma2p(e1lo, e1hi, t1lo, t1hi, q1.z, q1.w, e1lo, e1hi);
        }

        float s[4];
        s[0] = e0lo + o0lo; s[1] = e0hi + o0hi;
        s[2] = e1lo + o1lo; s[3] = e1hi + o1hi;

        #pragma unroll
        for (int k = 0; k < 4; k++) {
            const float sk  = s[k] + b2s;
            const bool  act = p[k] <= 0.5f;                     // uses pre-reset p
            const float un  = (sk <= ATH) ? -1.0f : 1.0f;
            const float vn  = vr[k] + un * 0.0015f - 0.0025f * cosf(3.0f * pr[k]);
            const float pn  = pr[k] + vn;
            if (act) {
                p[k] = pn; v[k] = vn; u[k] = un;
                skeep[k]   = sk;
                everact[k] = true;
            }
        }
    }

    #pragma unroll
    for (int k = 0; k < 4; k++) {
        const float ak = everact[k] ? tanhf(skeep[k]) : a[k];
        float4 st;
        st.x = p[k]; st.y = v[k]; st.z = u[k]; st.w = ak;
        ((float4*)out)[g + k * NTOT] = st;
    }
}

extern "C" void kernel_launch(void* const* d_in, const int* in_sizes, int n_in,
                              void* d_out, int out_size)
{
    const float* x  = (const float*)d_in[0];
    const float* W1 = (const float*)d_in[1];
    const float* b1 = (const float*)d_in[2];
    const float* W2 = (const float*)d_in[3];
    const float* b2 = (const float*)d_in[4];
    const int*   ns = (const int*)d_in[5];

    mc_kernel<<<NBLK, NTHR>>>(x, W1, b1, W2, b2, ns, (float*)d_out);
}

// round 2
// speedup vs baseline: 1.3208x; 1.3208x over previous
#include <cuda_runtime.h>
#include <cstdint>

#define NBLK 128
#define NTHR 256
#define NTOT (NBLK * NTHR)   // 32768 threads, 2 particles each = 65536
#define LHID 64

// Packed fp32x2 FMA (Blackwell FFMA2). Scalar halves in/out; ptxas coalesces
// the mov.b64 pack/unpack into aligned register pairs.
__device__ __forceinline__ void fma2p(float &dlo, float &dhi,
                                      float alo, float ahi,
                                      float blo, float bhi,
                                      float clo, float chi)
{
    asm("{\n\t"
        ".reg .b64 pa, pb, pc;\n\t"
        "mov.b64 pa, {%2, %3};\n\t"
        "mov.b64 pb, {%4, %5};\n\t"
        "mov.b64 pc, {%6, %7};\n\t"
        "fma.rn.f32x2 pc, pa, pb, pc;\n\t"
        "mov.b64 {%0, %1}, pc;\n\t"
        "}"
        : "=f"(dlo), "=f"(dhi)
        : "f"(alo), "f"(ahi), "f"(blo), "f"(bhi), "f"(clo), "f"(chi));
}

__global__ __launch_bounds__(NTHR, 1)
void mc_kernel(const float* __restrict__ x,
               const float* __restrict__ W1,
               const float* __restrict__ b1,
               const float* __restrict__ W2,
               const float* __restrict__ b2,
               const int*   __restrict__ n_steps,
               float*       __restrict__ out)
{
    // Weights duplicated pairwise so LDS.128 lands {w,w} in an aligned reg pair.
    __shared__ float sw[LHID * 8];   // per j: {A,A,B,B,b,b,C,C}

    const int tid = threadIdx.x;
    if (tid < LHID) {
        const float A  = W1[tid];          // W1[0][j]
        const float Bw = W1[LHID + tid];   // W1[1][j]
        const float bb = b1[tid];
        const float C  = W2[tid];          // W2[j][0]
        float* w = &sw[tid * 8];
        w[0] = A;  w[1] = A;
        w[2] = Bw; w[3] = Bw;
        w[4] = bb; w[5] = bb;
        w[6] = C;  w[7] = C;
    }
    const float b2s = b2[0];
    const int   T   = n_steps[0];
    __syncthreads();

    const int g = blockIdx.x * NTHR + tid;

    float p[2], v[2], u[2], a[2], skeep[2];
    bool everact[2];
    #pragma unroll
    for (int k = 0; k < 2; k++) {
        float4 st = ((const float4*)x)[g + k * NTOT];
        p[k] = st.x; v[k] = st.y; u[k] = st.z; a[k] = st.w;
        skeep[k]   = 0.0f;
        everact[k] = false;
    }

    // atanh(0.5): tanh(s+b2) <= 0.5  <=>  s+b2 <= ATH (monotone)
    const float ATH = 0.5493061443340549f;

    for (int t = 0; t < T; t++) {
        float pr[2], vr[2];
        #pragma unroll
        for (int k = 0; k < 2; k++) {
            const bool rst = p[k] <= -1.2f;
            pr[k] = rst ? -1.2f : p[k];
            vr[k] = rst ? 0.0f  : v[k];
        }

        // 2 accumulators (even/odd j) -> 2 independent FMA chains
        float elo = 0.f, ehi = 0.f, olo = 0.f, ohi = 0.f;

        #pragma unroll
        for (int j = 0; j < LHID; j++) {
            const float4 q0 = *(const float4*)&sw[j * 8];      // {A,A,B,B}
            const float4 q1 = *(const float4*)&sw[j * 8 + 4];  // {b,b,C,C}

            float tlo, thi;
            fma2p(tlo, thi, pr[0], pr[1], q0.x, q0.y, q1.x, q1.y); // p*A+b
            fma2p(tlo, thi, vr[0], vr[1], q0.z, q0.w, tlo, thi);   // +v*B
            tlo = fmaxf(tlo, 0.0f);
            thi = fmaxf(thi, 0.0f);
            if (j & 1) fma2p(olo, ohi, tlo, thi, q1.z, q1.w, olo, ohi);
            else       fma2p(elo, ehi, tlo, thi, q1.z, q1.w, elo, ehi);
        }

        float s[2];
        s[0] = elo + olo; s[1] = ehi + ohi;

        #pragma unroll
        for (int k = 0; k < 2; k++) {
            const float sk  = s[k] + b2s;
            const bool  act = p[k] <= 0.5f;                     // uses pre-reset p
            const float un  = (sk <= ATH) ? -1.0f : 1.0f;
            const float vn  = vr[k] + un * 0.0015f - 0.0025f * cosf(3.0f * pr[k]);
            const float pn  = pr[k] + vn;
            if (act) {
                p[k] = pn; v[k] = vn; u[k] = un;
                skeep[k]   = sk;
                everact[k] = true;
            }
        }
    }

    #pragma unroll
    for (int k = 0; k < 2; k++) {
        const float ak = everact[k] ? tanhf(skeep[k]) : a[k];
        float4 st;
        st.x = p[k]; st.y = v[k]; st.z = u[k]; st.w = ak;
        ((float4*)out)[g + k * NTOT] = st;
    }
}

extern "C" void kernel_launch(void* const* d_in, const int* in_sizes, int n_in,
                              void* d_out, int out_size)
{
    const float* x  = (const float*)d_in[0];
    const float* W1 = (const float*)d_in[1];
    const float* b1 = (const float*)d_in[2];
    const float* W2 = (const float*)d_in[3];
    const float* b2 = (const float*)d_in[4];
    const int*   ns = (const int*)d_in[5];

    mc_kernel<<<NBLK, NTHR>>>(x, W1, b1, W2, b2, ns, (float*)d_out);
}

// round 3
// speedup vs baseline: 2.0006x; 1.5147x over previous
#include <cuda_runtime.h>
#include <cstdint>

#define NBLK 128
#define NTHR 256
#define NTOT (NBLK * NTHR)   // 32768 threads, 2 particles each = 65536
#define LHID 64

// Packed fp32x2 FMA (Blackwell FFMA2). Scalar halves in/out; ptxas coalesces
// the mov.b64 pack/unpack into aligned register pairs.
__device__ __forceinline__ void fma2p(float &dlo, float &dhi,
                                      float alo, float ahi,
                                      float blo, float bhi,
                                      float clo, float chi)
{
    asm("{\n\t"
        ".reg .b64 pa, pb, pc;\n\t"
        "mov.b64 pa, {%2, %3};\n\t"
        "mov.b64 pb, {%4, %5};\n\t"
        "mov.b64 pc, {%6, %7};\n\t"
        "fma.rn.f32x2 pc, pa, pb, pc;\n\t"
        "mov.b64 {%0, %1}, pc;\n\t"
        "}"
        : "=f"(dlo), "=f"(dhi)
        : "f"(alo), "f"(ahi), "f"(blo), "f"(bhi), "f"(clo), "f"(chi));
}

__global__ __launch_bounds__(NTHR, 1)
void mc_kernel(const float* __restrict__ x,
               const float* __restrict__ W1,
               const float* __restrict__ b1,
               const float* __restrict__ W2,
               const float* __restrict__ b2,
               const int*   __restrict__ n_steps,
               float*       __restrict__ out)
{
    // Weights duplicated pairwise so LDS.128 lands {w,w} in an aligned reg pair.
    __shared__ float sw[LHID * 8];   // per j: {A,A,B,B,b,b,C,C}

    const int tid = threadIdx.x;
    if (tid < LHID) {
        const float A  = W1[tid];          // W1[0][j]
        const float Bw = W1[LHID + tid];   // W1[1][j]
        const float bb = b1[tid];
        const float C  = W2[tid];          // W2[j][0]
        float* w = &sw[tid * 8];
        w[0] = A;  w[1] = A;
        w[2] = Bw; w[3] = Bw;
        w[4] = bb; w[5] = bb;
        w[6] = C;  w[7] = C;
    }
    const float b2s = b2[0];
    const int   T   = n_steps[0];
    __syncthreads();

    const int g = blockIdx.x * NTHR + tid;

    float p[2], v[2], u[2], a[2], skeep[2];
    bool everact[2];
    #pragma unroll
    for (int k = 0; k < 2; k++) {
        float4 st = ((const float4*)x)[g + k * NTOT];
        p[k] = st.x; v[k] = st.y; u[k] = st.z; a[k] = st.w;
        skeep[k]   = 0.0f;
        everact[k] = false;
    }

    // atanh(0.5): tanh(s+b2) <= 0.5  <=>  s+b2 <= ATH (monotone)
    const float ATH = 0.5493061443340549f;

    for (int t = 0; t < T; t++) {
        float pr[2], vr[2];
        #pragma unroll
        for (int k = 0; k < 2; k++) {
            const bool rst = p[k] <= -1.2f;
            pr[k] = rst ? -1.2f : p[k];
            vr[k] = rst ? 0.0f  : v[k];
        }

        // 2 accumulators (even/odd j) -> 2 independent FMA chains
        float elo = 0.f, ehi = 0.f, olo = 0.f, ohi = 0.f;

        // Bounded unroll: keeps only ~8 iterations of weight loads live so
        // ptxas doesn't front-batch all 64 (which spilled at 255 regs).
        #pragma unroll 8
        for (int j = 0; j < LHID; j++) {
            const float4 q0 = *(const float4*)&sw[j * 8];      // {A,A,B,B}
            const float4 q1 = *(const float4*)&sw[j * 8 + 4];  // {b,b,C,C}

            float tlo, thi;
            fma2p(tlo, thi, pr[0], pr[1], q0.x, q0.y, q1.x, q1.y); // p*A+b
            fma2p(tlo, thi, vr[0], vr[1], q0.z, q0.w, tlo, thi);   // +v*B
            tlo = fmaxf(tlo, 0.0f);
            thi = fmaxf(thi, 0.0f);
            if (j & 1) fma2p(olo, ohi, tlo, thi, q1.z, q1.w, olo, ohi);
            else       fma2p(elo, ehi, tlo, thi, q1.z, q1.w, elo, ehi);
        }

        float s[2];
        s[0] = elo + olo; s[1] = ehi + ohi;

        #pragma unroll
        for (int k = 0; k < 2; k++) {
            const float sk  = s[k] + b2s;
            const bool  act = p[k] <= 0.5f;                     // uses pre-reset p
            const float un  = (sk <= ATH) ? -1.0f : 1.0f;
            const float vn  = vr[k] + un * 0.0015f - 0.0025f * cosf(3.0f * pr[k]);
            const float pn  = pr[k] + vn;
            if (act) {
                p[k] = pn; v[k] = vn; u[k] = un;
                skeep[k]   = sk;
                everact[k] = true;
            }
        }
    }

    #pragma unroll
    for (int k = 0; k < 2; k++) {
        const float ak = everact[k] ? tanhf(skeep[k]) : a[k];
        float4 st;
        st.x = p[k]; st.y = v[k]; st.z = u[k]; st.w = ak;
        ((float4*)out)[g + k * NTOT] = st;
    }
}

extern "C" void kernel_launch(void* const* d_in, const int* in_sizes, int n_in,
                              void* d_out, int out_size)
{
    const float* x  = (const float*)d_in[0];
    const float* W1 = (const float*)d_in[1];
    const float* b1 = (const float*)d_in[2];
    const float* W2 = (const float*)d_in[3];
    const float* b2 = (const float*)d_in[4];
    const int*   ns = (const int*)d_in[5];

    mc_kernel<<<NBLK, NTHR>>>(x, W1, b1, W2, b2, ns, (float*)d_out);
}

// round 8
// speedup vs baseline: 2.6967x; 1.3479x over previous
#include <cuda_runtime.h>
#include <cstdint>

#define NBLK 128
#define NTHR 128
#define NTOT (NBLK * NTHR)   // 16384 threads, 4 particles each = 65536
#define LHID 64

// Packed fp32x2 FMA (Blackwell FFMA2). Scalar halves in/out; ptxas coalesces
// the mov.b64 pack/unpack into aligned register pairs.
__device__ __forceinline__ void fma2p(float &dlo, float &dhi,
                                      float alo, float ahi,
                                      float blo, float bhi,
                                      float clo, float chi)
{
    asm("{\n\t"
        ".reg .b64 pa, pb, pc;\n\t"
        "mov.b64 pa, {%2, %3};\n\t"
        "mov.b64 pb, {%4, %5};\n\t"
        "mov.b64 pc, {%6, %7};\n\t"
        "fma.rn.f32x2 pc, pa, pb, pc;\n\t"
        "mov.b64 {%0, %1}, pc;\n\t"
        "}"
        : "=f"(dlo), "=f"(dhi)
        : "f"(alo), "f"(ahi), "f"(blo), "f"(bhi), "f"(clo), "f"(chi));
}

__global__ __launch_bounds__(NTHR, 1)
void mc_kernel(const float* __restrict__ x,
               const float* __restrict__ W1,
               const float* __restrict__ b1,
               const float* __restrict__ W2,
               const float* __restrict__ b2,
               const int*   __restrict__ n_steps,
               float*       __restrict__ out)
{
    // Weights duplicated pairwise so LDS.128 lands {w,w} in an aligned reg pair.
    __shared__ float sw[LHID * 8];   // per j: {A,A,B,B,b,b,C,C}

    const int tid = threadIdx.x;
    if (tid < LHID) {
        const float A  = W1[tid];          // W1[0][j]
        const float Bw = W1[LHID + tid];   // W1[1][j]
        const float bb = b1[tid];
        const float C  = W2[tid];          // W2[j][0]
        float* w = &sw[tid * 8];
        w[0] = A;  w[1] = A;
        w[2] = Bw; w[3] = Bw;
        w[4] = bb; w[5] = bb;
        w[6] = C;  w[7] = C;
    }
    const float b2s = b2[0];
    const int   T   = n_steps[0];
    __syncthreads();

    const int g = blockIdx.x * NTHR + tid;

    float p[4], v[4], u[4], a[4], skeep[4];
    bool everact[4];
    #pragma unroll
    for (int k = 0; k < 4; k++) {
        float4 st = ((const float4*)x)[g + k * NTOT];
        p[k] = st.x; v[k] = st.y; u[k] = st.z; a[k] = st.w;
        skeep[k]   = 0.0f;
        everact[k] = false;
    }

    // atanh(0.5): tanh(s+b2) <= 0.5  <=>  s+b2 <= ATH (monotone)
    const float ATH = 0.5493061443340549f;

    for (int t = 0; t < T; t++) {
        float pr[4], vr[4];
        #pragma unroll
        for (int k = 0; k < 4; k++) {
            const bool rst = p[k] <= -1.2f;
            pr[k] = rst ? -1.2f : p[k];
            vr[k] = rst ? 0.0f  : v[k];
        }

        // 4 independent FMA chains: (even/odd j) x (pair0/pair1)
        float e0lo = 0.f, e0hi = 0.f, o0lo = 0.f, o0hi = 0.f;
        float e1lo = 0.f, e1hi = 0.f, o1lo = 0.f, o1hi = 0.f;

        // Bounded unroll: keeps only ~8 iterations of weight loads live so
        // ptxas doesn't front-batch all 64 (which spilled at 255 regs).
        #pragma unroll 8
        for (int j = 0; j < LHID; j++) {
            const float4 q0 = *(const float4*)&sw[j * 8];      // {A,A,B,B}
            const float4 q1 = *(const float4*)&sw[j * 8 + 4];  // {b,b,C,C}

            // pair 0: particles 0,1
            float t0lo, t0hi;
            fma2p(t0lo, t0hi, pr[0], pr[1], q0.x, q0.y, q1.x, q1.y); // p*A+b
            fma2p(t0lo, t0hi, vr[0], vr[1], q0.z, q0.w, t0lo, t0hi); // +v*B
            t0lo = fmaxf(t0lo, 0.0f);
            t0hi = fmaxf(t0hi, 0.0f);
            if (j & 1) fma2p(o0lo, o0hi, t0lo, t0hi, q1.z, q1.w, o0lo, o0hi);
            else       fma2p(e0lo, e0hi, t0lo, t0hi, q1.z, q1.w, e0lo, e0hi);

            // pair 1: particles 2,3
            float t1lo, t1hi;
            fma2p(t1lo, t1hi, pr[2], pr[3], q0.x, q0.y, q1.x, q1.y);
            fma2p(t1lo, t1hi, vr[2], vr[3], q0.z, q0.w, t1lo, t1hi);
            t1lo = fmaxf(t1lo, 0.0f);
            t1hi = fmaxf(t1hi, 0.0f);
            if (j & 1) fma2p(o1lo, o1hi, t1lo, t1hi, q1.z, q1.w, o1lo, o1hi);
            else       fma2p(e1lo, e1hi, t1lo, t1hi, q1.z, q1.w, e1lo, e1hi);
        }

        float s[4];
        s[0] = e0lo + o0lo; s[1] = e0hi + o0hi;
        s[2] = e1lo + o1lo; s[3] = e1hi + o1hi;

        #pragma unroll
        for (int k = 0; k < 4; k++) {
            const float sk  = s[k] + b2s;
            const bool  act = p[k] <= 0.5f;                     // uses pre-reset p
            const float un  = (sk <= ATH) ? -1.0f : 1.0f;
            const float vn  = vr[k] + un * 0.0015f - 0.0025f * cosf(3.0f * pr[k]);
            const float pn  = pr[k] + vn;
            if (act) {
                p[k] = pn; v[k] = vn; u[k] = un;
                skeep[k]   = sk;
                everact[k] = true;
            }
        }
    }

    #pragma unroll
    for (int k = 0; k < 4; k++) {
        const float ak = everact[k] ? tanhf(skeep[k]) : a[k];
        float4 st;
        st.x = p[k]; st.y = v[k]; st.z = u[k]; st.w = ak;
        ((float4*)out)[g + k * NTOT] = st;
    }
}

extern "C" void kernel_launch(void* const* d_in, const int* in_sizes, int n_in,
                              void* d_out, int out_size)
{
    const float* x  = (const float*)d_in[0];
    const float* W1 = (const float*)d_in[1];
    const float* b1 = (const float*)d_in[2];
    const float* W2 = (const float*)d_in[3];
    const float* b2 = (const float*)d_in[4];
    const int*   ns = (const int*)d_in[5];

    mc_kernel<<<NBLK, NTHR>>>(x, W1, b1, W2, b2, ns, (float*)d_out);
}

// round 9
// speedup vs baseline: 2.7730x; 1.0283x over previous
#include <cuda_runtime.h>
#include <cstdint>

#define NBLK 128
#define NTHR 128
#define NTOT (NBLK * NTHR)   // 16384 threads, 4 particles each = 65536
#define LHID 64

typedef unsigned long long u64;

// Pack two fp32 into a b64 register pair.
__device__ __forceinline__ u64 pk2(float lo, float hi)
{
    u64 r;
    asm("mov.b64 %0, {%1, %2};" : "=l"(r) : "f"(lo), "f"(hi));
    return r;
}
__device__ __forceinline__ void upk2(float &lo, float &hi, u64 x)
{
    asm("mov.b64 {%0, %1}, %2;" : "=f"(lo), "=f"(hi) : "l"(x));
}

// Packed fp32x2 FMA operating directly on b64 values: no pack/unpack at the
// call boundary, so accumulator chains stay in fixed register pairs.
__device__ __forceinline__ u64 fma2(u64 a, u64 b, u64 c)
{
    u64 d;
    asm("fma.rn.f32x2 %0, %1, %2, %3;" : "=l"(d) : "l"(a), "l"(b), "l"(c));
    return d;
}

// relu on both halves; internal movs coalesce to pair-half aliases in SASS.
__device__ __forceinline__ u64 relu2(u64 x)
{
    u64 r;
    asm("{\n\t"
        ".reg .f32 lo, hi;\n\t"
        "mov.b64 {lo, hi}, %1;\n\t"
        "max.f32 lo, lo, 0f00000000;\n\t"
        "max.f32 hi, hi, 0f00000000;\n\t"
        "mov.b64 %0, {lo, hi};\n\t"
        "}" : "=l"(r) : "l"(x));
    return r;
}

__global__ __launch_bounds__(NTHR, 1)
void mc_kernel(const float* __restrict__ x,
               const float* __restrict__ W1,
               const float* __restrict__ b1,
               const float* __restrict__ W2,
               const float* __restrict__ b2,
               const int*   __restrict__ n_steps,
               float*       __restrict__ out)
{
    // Weights duplicated pairwise; per j: {A,A,B,B,b,b,C,C} = 2 x ulonglong2.
    __shared__ float sw[LHID * 8];

    const int tid = threadIdx.x;
    if (tid < LHID) {
        const float A  = W1[tid];          // W1[0][j]
        const float Bw = W1[LHID + tid];   // W1[1][j]
        const float bb = b1[tid];
        const float C  = W2[tid];          // W2[j][0]
        float* w = &sw[tid * 8];
        w[0] = A;  w[1] = A;
        w[2] = Bw; w[3] = Bw;
        w[4] = bb; w[5] = bb;
        w[6] = C;  w[7] = C;
    }
    const float b2s = b2[0];
    const int   T   = n_steps[0];
    __syncthreads();

    const int g = blockIdx.x * NTHR + tid;

    float p[4], v[4], u[4], a[4], skeep[4];
    bool everact[4];
    #pragma unroll
    for (int k = 0; k < 4; k++) {
        float4 st = ((const float4*)x)[g + k * NTOT];
        p[k] = st.x; v[k] = st.y; u[k] = st.z; a[k] = st.w;
        skeep[k]   = 0.0f;
        everact[k] = false;
    }

    // atanh(0.5): tanh(s+b2) <= 0.5  <=>  s+b2 <= ATH (monotone)
    const float ATH = 0.5493061443340549f;

    const ulonglong2* swp = (const ulonglong2*)sw;

    for (int t = 0; t < T; t++) {
        float pr[4], vr[4];
        #pragma unroll
        for (int k = 0; k < 4; k++) {
            const bool rst = p[k] <= -1.2f;
            pr[k] = rst ? -1.2f : p[k];
            vr[k] = rst ? 0.0f  : v[k];
        }

        // Pack particle-pair inputs once per step.
        const u64 pr01 = pk2(pr[0], pr[1]);
        const u64 vr01 = pk2(vr[0], vr[1]);
        const u64 pr23 = pk2(pr[2], pr[3]);
        const u64 vr23 = pk2(vr[2], vr[3]);

        // 4 independent FMA chains: (even/odd j) x (pair0/pair1)
        u64 e0 = 0ull, o0 = 0ull, e1 = 0ull, o1 = 0ull;

        // Bounded unroll: keeps only ~8 iterations of weight loads live so
        // ptxas doesn't front-batch all 64 (which spilled at 255 regs).
        #pragma unroll 8
        for (int j = 0; j < LHID; j++) {
            const ulonglong2 w0 = swp[j * 2];       // {AA, BB}
            const ulonglong2 w1 = swp[j * 2 + 1];   // {bb, CC}

            // pair 0: particles 0,1
            u64 t0 = fma2(pr01, w0.x, w1.x);   // p*A + b
            t0     = fma2(vr01, w0.y, t0);     // + v*B
            t0     = relu2(t0);
            if (j & 1) o0 = fma2(t0, w1.y, o0);
            else       e0 = fma2(t0, w1.y, e0);

            // pair 1: particles 2,3
            u64 t1 = fma2(pr23, w0.x, w1.x);
            t1     = fma2(vr23, w0.y, t1);
            t1     = relu2(t1);
            if (j & 1) o1 = fma2(t1, w1.y, o1);
            else       e1 = fma2(t1, w1.y, e1);
        }

        float s[4];
        {
            float elo, ehi, olo, ohi;
            upk2(elo, ehi, e0); upk2(olo, ohi, o0);
            s[0] = elo + olo; s[1] = ehi + ohi;
            upk2(elo, ehi, e1); upk2(olo, ohi, o1);
            s[2] = elo + olo; s[3] = ehi + ohi;
        }

        #pragma unroll
        for (int k = 0; k < 4; k++) {
            const float sk  = s[k] + b2s;
            const bool  act = p[k] <= 0.5f;                     // uses pre-reset p
            const float un  = (sk <= ATH) ? -1.0f : 1.0f;
            const float vn  = vr[k] + un * 0.0015f - 0.0025f * cosf(3.0f * pr[k]);
            const float pn  = pr[k] + vn;
            if (act) {
                p[k] = pn; v[k] = vn; u[k] = un;
                skeep[k]   = sk;
                everact[k] = true;
            }
        }
    }

    #pragma unroll
    for (int k = 0; k < 4; k++) {
        const float ak = everact[k] ? tanhf(skeep[k]) : a[k];
        float4 st;
        st.x = p[k]; st.y = v[k]; st.z = u[k]; st.w = ak;
        ((float4*)out)[g + k * NTOT] = st;
    }
}

extern "C" void kernel_launch(void* const* d_in, const int* in_sizes, int n_in,
                              void* d_out, int out_size)
{
    const float* x  = (const float*)d_in[0];
    const float* W1 = (const float*)d_in[1];
    const float* b1 = (const float*)d_in[2];
    const float* W2 = (const float*)d_in[3];
    const float* b2 = (const float*)d_in[4];
    const int*   ns = (const int*)d_in[5];

    mc_kernel<<<NBLK, NTHR>>>(x, W1, b1, W2, b2, ns, (float*)d_out);
}

// round 12
// speedup vs baseline: 3.3340x; 1.2023x over previous
#include <cuda_runtime.h>
#include <cstdint>

#define NBLK 148
#define NTHR 128
#define NTOT (NBLK * NTHR)   // 18944 threads, 4 particle-slots each = 75776 (>= 65536, tail masked)
#define NPART 65536
#define LHID 64

typedef unsigned long long u64;

// Pack two fp32 into a b64 register pair.
__device__ __forceinline__ u64 pk2(float lo, float hi)
{
    u64 r;
    asm("mov.b64 %0, {%1, %2};" : "=l"(r) : "f"(lo), "f"(hi));
    return r;
}
__device__ __forceinline__ void upk2(float &lo, float &hi, u64 x)
{
    asm("mov.b64 {%0, %1}, %2;" : "=f"(lo), "=f"(hi) : "l"(x));
}

// Packed fp32x2 FMA operating directly on b64 values.
__device__ __forceinline__ u64 fma2(u64 a, u64 b, u64 c)
{
    u64 d;
    asm("fma.rn.f32x2 %0, %1, %2, %3;" : "=l"(d) : "l"(a), "l"(b), "l"(c));
    return d;
}

// relu on both halves; internal movs coalesce to pair-half aliases in SASS.
__device__ __forceinline__ u64 relu2(u64 x)
{
    u64 r;
    asm("{\n\t"
        ".reg .f32 lo, hi;\n\t"
        "mov.b64 {lo, hi}, %1;\n\t"
        "max.f32 lo, lo, 0f00000000;\n\t"
        "max.f32 hi, hi, 0f00000000;\n\t"
        "mov.b64 %0, {lo, hi};\n\t"
        "}" : "=l"(r) : "l"(x));
    return r;
}

__global__ __launch_bounds__(NTHR, 1)
void mc_kernel(const float* __restrict__ x,
               const float* __restrict__ W1,
               const float* __restrict__ b1,
               const float* __restrict__ W2,
               const float* __restrict__ b2,
               const int*   __restrict__ n_steps,
               float*       __restrict__ out)
{
    // Weights duplicated pairwise; per j: {A,A,B,B,b,b,C,C} = 2 x ulonglong2.
    __shared__ float sw[LHID * 8];

    const int tid = threadIdx.x;
    if (tid < LHID) {
        const float A  = W1[tid];          // W1[0][j]
        const float Bw = W1[LHID + tid];   // W1[1][j]
        const float bb = b1[tid];
        const float C  = W2[tid];          // W2[j][0]
        float* w = &sw[tid * 8];
        w[0] = A;  w[1] = A;
        w[2] = Bw; w[3] = Bw;
        w[4] = bb; w[5] = bb;
        w[6] = C;  w[7] = C;
    }
    const float b2s = b2[0];
    const int   T   = n_steps[0];
    __syncthreads();

    const int g = blockIdx.x * NTHR + tid;

    // Slot k handles particle g + k*NTOT; tail slots clamp the load index
    // (redundant compute) and mask the store.
    int  idx[4];
    bool valid[4];
    float p[4], v[4], u[4], a[4], skeep[4];
    bool everact[4];
    #pragma unroll
    for (int k = 0; k < 4; k++) {
        const int raw = g + k * NTOT;
        valid[k] = raw < NPART;
        idx[k]   = valid[k] ? raw : (NPART - 1);
        float4 st = ((const float4*)x)[idx[k]];
        p[k] = st.x; v[k] = st.y; u[k] = st.z; a[k] = st.w;
        skeep[k]   = 0.0f;
        everact[k] = false;
    }

    // atanh(0.5): tanh(s+b2) <= 0.5  <=>  s+b2 <= ATH (monotone)
    const float ATH = 0.5493061443340549f;

    const ulonglong2* swp = (const ulonglong2*)sw;

    for (int t = 0; t < T; t++) {
        float pr[4], vr[4];
        #pragma unroll
        for (int k = 0; k < 4; k++) {
            const bool rst = p[k] <= -1.2f;
            pr[k] = rst ? -1.2f : p[k];
            vr[k] = rst ? 0.0f  : v[k];
        }

        // Pack particle-pair inputs once per step.
        const u64 pr01 = pk2(pr[0], pr[1]);
        const u64 vr01 = pk2(vr[0], vr[1]);
        const u64 pr23 = pk2(pr[2], pr[3]);
        const u64 vr23 = pk2(vr[2], vr[3]);

        // 4 independent FMA chains: (even/odd j) x (pair0/pair1)
        u64 e0 = 0ull, o0 = 0ull, e1 = 0ull, o1 = 0ull;

        // Unroll 16: ~32 LDS.128 batched per block, 32 independent FMA chains
        // in the scheduling window; regs stay well under the 255 spill cliff.
        #pragma unroll 16
        for (int j = 0; j < LHID; j++) {
            const ulonglong2 w0 = swp[j * 2];       // {AA, BB}
            const ulonglong2 w1 = swp[j * 2 + 1];   // {bb, CC}

            // pair 0: particles 0,1
            u64 t0 = fma2(pr01, w0.x, w1.x);   // p*A + b
            t0     = fma2(vr01, w0.y, t0);     // + v*B
            t0     = relu2(t0);
            if (j & 1) o0 = fma2(t0, w1.y, o0);
            else       e0 = fma2(t0, w1.y, e0);

            // pair 1: particles 2,3
            u64 t1 = fma2(pr23, w0.x, w1.x);
            t1     = fma2(vr23, w0.y, t1);
            t1     = relu2(t1);
            if (j & 1) o1 = fma2(t1, w1.y, o1);
            else       e1 = fma2(t1, w1.y, e1);
        }

        float s[4];
        {
            float elo, ehi, olo, ohi;
            upk2(elo, ehi, e0); upk2(olo, ohi, o0);
            s[0] = elo + olo; s[1] = ehi + ohi;
            upk2(elo, ehi, e1); upk2(olo, ohi, o1);
            s[2] = elo + olo; s[3] = ehi + ohi;
        }

        #pragma unroll
        for (int k = 0; k < 4; k++) {
            const float sk  = s[k] + b2s;
            const bool  act = p[k] <= 0.5f;                     // uses pre-reset p
            const float un  = (sk <= ATH) ? -1.0f : 1.0f;
            const float vn  = vr[k] + un * 0.0015f - 0.0025f * __cosf(3.0f * pr[k]);
            const float pn  = pr[k] + vn;
            if (act) {
                p[k] = pn; v[k] = vn; u[k] = un;
                skeep[k]   = sk;
                everact[k] = true;
            }
        }
    }

    #pragma unroll
    for (int k = 0; k < 4; k++) {
        if (valid[k]) {
            const float ak = everact[k] ? tanhf(skeep[k]) : a[k];
            float4 st;
            st.x = p[k]; st.y = v[k]; st.z = u[k]; st.w = ak;
            ((float4*)out)[idx[k]] = st;
        }
    }
}

extern "C" void kernel_launch(void* const* d_in, const int* in_sizes, int n_in,
                              void* d_out, int out_size)
{
    const float* x  = (const float*)d_in[0];
    const float* W1 = (const float*)d_in[1];
    const float* b1 = (const float*)d_in[2];
    const float* W2 = (const float*)d_in[3];
    const float* b2 = (const float*)d_in[4];
    const int*   ns = (const int*)d_in[5];

    mc_kernel<<<NBLK, NTHR>>>(x, W1, b1, W2, b2, ns, (float*)d_out);
}